// round 3
// baseline (speedup 1.0000x reference)
#include <cuda_runtime.h>

#define N_NODES 160000
#define NODES_PER_GRAPH 20000
#define N_GRAPHS 8
#define N_EDGES 5120000
#define HID 16
#define O1 4000
#define O2 800
#define O3 160
#define NOUT 10

// -------- scratch (device globals: no allocation allowed) --------
__device__ __align__(16) float d_agg1[N_NODES];
__device__ __align__(16) float d_agg2[N_NODES];
__device__ __align__(16) float d_p[N_NODES];
__device__ __align__(16) float d_q[N_NODES];
// batch-major activations: [b][k]
__device__ __align__(16) float d_gT[N_GRAPHS * NODES_PER_GRAPH];
__device__ __align__(16) float d_h1T[N_GRAPHS * O1];
__device__ __align__(16) float d_h2T[N_GRAPHS * O2];
__device__ __align__(16) float d_h3T[N_GRAPHS * O3];

// -------- zero accumulators ----------------------------------------------
__global__ void k_zero() {
    int i = blockIdx.x * blockDim.x + threadIdx.x;
    if (i < N_NODES) { d_agg1[i] = 0.f; d_agg2[i] = 0.f; }
}

// -------- scalar edge scatter: agg[tgt] += ew * val[src] -----------------
__global__ void k_scatter(const int* __restrict__ src, const int* __restrict__ tgt,
                          const float* __restrict__ ew, const float* __restrict__ val_in,
                          int pass) {
    const float* __restrict__ val = (pass == 0) ? val_in : d_p;
    float* __restrict__ agg = (pass == 0) ? d_agg1 : d_agg2;
    int t = blockIdx.x * blockDim.x + threadIdx.x;
    int e0 = t * 4;
    if (e0 + 3 < N_EDGES) {
        int4   s = *reinterpret_cast<const int4*>(src + e0);
        int4   g = *reinterpret_cast<const int4*>(tgt + e0);
        float4 w = *reinterpret_cast<const float4*>(ew + e0);
        atomicAdd(&agg[g.x], w.x * __ldg(&val[s.x]));
        atomicAdd(&agg[g.y], w.y * __ldg(&val[s.y]));
        atomicAdd(&agg[g.z], w.z * __ldg(&val[s.z]));
        atomicAdd(&agg[g.w], w.w * __ldg(&val[s.w]));
    } else if (e0 < N_EDGES) {
        for (int e = e0; e < N_EDGES; e++)
            atomicAdd(&agg[tgt[e]], ew[e] * __ldg(&val[src[e]]));
    }
}

// -------- per-node layer-1 + fold layer-2 matmuls to scalars -------------
__global__ void k_node1(const float* __restrict__ x,
                        const float* __restrict__ Wr1, const float* __restrict__ br1,
                        const float* __restrict__ Ws1, const float* __restrict__ Wr2,
                        const float* __restrict__ Ws2) {
    __shared__ float swr1[HID], sbr1[HID], sws1[HID], swr2[HID], sws2[HID];
    if (threadIdx.x < HID) {
        swr1[threadIdx.x] = Wr1[threadIdx.x];
        sbr1[threadIdx.x] = br1[threadIdx.x];
        sws1[threadIdx.x] = Ws1[threadIdx.x];
        swr2[threadIdx.x] = Wr2[threadIdx.x];
        sws2[threadIdx.x] = Ws2[threadIdx.x];
    }
    __syncthreads();
    int n = blockIdx.x * blockDim.x + threadIdx.x;
    if (n >= N_NODES) return;
    float a = d_agg1[n];
    float xv = x[n];
    float p = 0.f, q = 0.f;
#pragma unroll
    for (int f = 0; f < HID; f++) {
        float h = fmaf(a, swr1[f], fmaf(xv, sws1[f], sbr1[f]));
        h = fmaxf(h, 0.f);
        p = fmaf(swr2[f], h, p);
        q = fmaf(sws2[f], h, q);
    }
    d_p[n] = p;
    d_q[n] = q;
}

// -------- per-node layer-2 epilogue; write gT batch-major [b][i] ---------
__global__ void k_node2(const float* __restrict__ br2) {
    int n = blockIdx.x * blockDim.x + threadIdx.x;
    if (n >= N_NODES) return;
    float h2 = d_agg2[n] + __ldg(br2) + d_q[n];
    int b = n / NODES_PER_GRAPH;
    int i = n - b * NODES_PER_GRAPH;
    d_gT[b * NODES_PER_GRAPH + i] = h2;
}

// -------- dense layer: out[b][o] = act( sum_k W[o][k] * in[b][k] + bias[o] )
// 16 output rows per block (two 8-row halves), gT tile staged in smem once
// per block. All loads float4. K must be a multiple of 4; M a multiple of 16.
#define GTK 512
template <bool RELU>
__global__ void __launch_bounds__(256)
k_gemmT(const float* __restrict__ W, const float* __restrict__ bias,
        const float* __restrict__ inT, float* __restrict__ outT, int K, int M) {
    const int tid  = threadIdx.x;
    const int half = tid >> 7;       // 0/1
    const int lane = tid & 127;      // 0..127
    const int o0   = blockIdx.x * 16 + half * 8;

    __shared__ float sg[8][GTK];        // 16 KB activation tile
    __shared__ float sred[64 * 128];    // 32 KB reduction buffer

    float acc[8][8];
#pragma unroll
    for (int r = 0; r < 8; r++)
#pragma unroll
        for (int b = 0; b < 8; b++) acc[r][b] = 0.f;

    const int k4 = lane * 4;
    for (int kt = 0; kt < K; kt += GTK) {
        // cooperative tile load: 1024 float4 slots, 4 per thread
#pragma unroll
        for (int i = 0; i < 4; i++) {
            int f  = tid + i * 256;       // float4 slot index
            int b  = f >> 7;              // 0..7
            int kk = (f & 127) * 4;       // 0..508
            float4 v = make_float4(0.f, 0.f, 0.f, 0.f);
            int kg = kt + kk;
            if (kg < K)                   // K % 4 == 0 -> full vector valid
                v = *reinterpret_cast<const float4*>(inT + (size_t)b * K + kg);
            *reinterpret_cast<float4*>(&sg[b][kk]) = v;
        }
        __syncthreads();

        if (kt + k4 < K) {
            const float* Wp = W + (size_t)o0 * K + kt + k4;
            float4 w[8];
#pragma unroll
            for (int r = 0; r < 8; r++)
                w[r] = *reinterpret_cast<const float4*>(Wp + (size_t)r * K);
#pragma unroll
            for (int b = 0; b < 8; b++) {
                float4 g = *reinterpret_cast<const float4*>(&sg[b][k4]);
#pragma unroll
                for (int r = 0; r < 8; r++) {
                    acc[r][b] = fmaf(w[r].x, g.x, acc[r][b]);
                    acc[r][b] = fmaf(w[r].y, g.y, acc[r][b]);
                    acc[r][b] = fmaf(w[r].z, g.z, acc[r][b]);
                    acc[r][b] = fmaf(w[r].w, g.w, acc[r][b]);
                }
            }
        }
        __syncthreads();
    }

    // reduce 128 partials per output; halves sequential to reuse sred
    for (int h = 0; h < 2; h++) {
        __syncthreads();
        if (half == h) {
#pragma unroll
            for (int j = 0; j < 64; j++)
                sred[j * 128 + lane] = acc[j >> 3][j & 7];
        }
        __syncthreads();
        int j    = tid >> 2;   // 0..63 : which output
        int part = tid & 3;    // 0..3  : partial slice
        float v = 0.f;
#pragma unroll
        for (int t = 0; t < 32; t++) v += sred[j * 128 + part + t * 4];
        v += __shfl_down_sync(0xffffffffu, v, 2, 4);
        v += __shfl_down_sync(0xffffffffu, v, 1, 4);
        if (part == 0) {
            int r = j >> 3, b = j & 7;
            int o = blockIdx.x * 16 + h * 8 + r;
            float ov = v + __ldg(&bias[o]);
            if (RELU) ov = fmaxf(ov, 0.f);
            outT[(size_t)b * M + o] = ov;
        }
    }
}

// -------- final 10x160 layer + log_softmax (h3T batch-major) -------------
__global__ void k_final(const float* __restrict__ W4, const float* __restrict__ b4,
                        float* __restrict__ out) {
    __shared__ float logits[N_GRAPHS][NOUT];
    int tid = threadIdx.x;
    if (tid < N_GRAPHS * NOUT) {
        int o = tid / N_GRAPHS;
        int b = tid % N_GRAPHS;
        float v = __ldg(&b4[o]);
        for (int k = 0; k < O3; k++)
            v = fmaf(__ldg(&W4[o * O3 + k]), d_h3T[b * O3 + k], v);
        logits[b][o] = v;
    }
    __syncthreads();
    if (tid < N_GRAPHS) {
        float m = -1e30f;
#pragma unroll
        for (int o = 0; o < NOUT; o++) m = fmaxf(m, logits[tid][o]);
        float sum = 0.f;
#pragma unroll
        for (int o = 0; o < NOUT; o++) sum += expf(logits[tid][o] - m);
        float lse = m + logf(sum);
#pragma unroll
        for (int o = 0; o < NOUT; o++) out[tid * NOUT + o] = logits[tid][o] - lse;
    }
}

void launch_gemms(const float* W1, const float* b1, const float* W2, const float* b2,
                  const float* W3, const float* b3, const float* W4, const float* b4,
                  float* out) {
    static float *p_gT = nullptr, *p_h1 = nullptr, *p_h2 = nullptr, *p_h3 = nullptr;
    if (!p_gT) {
        cudaGetSymbolAddress((void**)&p_gT, d_gT);
        cudaGetSymbolAddress((void**)&p_h1, d_h1T);
        cudaGetSymbolAddress((void**)&p_h2, d_h2T);
        cudaGetSymbolAddress((void**)&p_h3, d_h3T);
    }
    k_gemmT<true ><<<O1 / 16, 256>>>(W1, b1, p_gT, p_h1, NODES_PER_GRAPH, O1);
    k_gemmT<true ><<<O2 / 16, 256>>>(W2, b2, p_h1, p_h2, O1, O2);
    k_gemmT<true ><<<O3 / 16, 256>>>(W3, b3, p_h2, p_h3, O2, O3);
    k_final<<<1, 128>>>(W4, b4, out);
}

extern "C" void kernel_launch(void* const* d_in, const int* in_sizes, int n_in,
                              void* d_out, int out_size) {
    const float* x   = (const float*)d_in[0];
    const float* ew  = (const float*)d_in[1];
    const float* Wr1 = (const float*)d_in[2];
    const float* br1 = (const float*)d_in[3];
    const float* Ws1 = (const float*)d_in[4];
    const float* Wr2 = (const float*)d_in[5];
    const float* br2 = (const float*)d_in[6];
    const float* Ws2 = (const float*)d_in[7];
    const float* W1  = (const float*)d_in[8];
    const float* b1  = (const float*)d_in[9];
    const float* W2  = (const float*)d_in[10];
    const float* b2  = (const float*)d_in[11];
    const float* W3  = (const float*)d_in[12];
    const float* b3  = (const float*)d_in[13];
    const float* W4  = (const float*)d_in[14];
    const float* b4  = (const float*)d_in[15];
    const int*   ei  = (const int*)d_in[16];
    float* out = (float*)d_out;

    const int* src = ei;
    const int* tgt = ei + N_EDGES;

    const int NODE_BLOCKS = (N_NODES + 255) / 256;
    const int EDGE_BLOCKS = (N_EDGES / 4 + 255) / 256;

    k_zero<<<NODE_BLOCKS, 256>>>();
    k_scatter<<<EDGE_BLOCKS, 256>>>(src, tgt, ew, x, 0);
    k_node1<<<NODE_BLOCKS, 256>>>(x, Wr1, br1, Ws1, Wr2, Ws2);
    k_scatter<<<EDGE_BLOCKS, 256>>>(src, tgt, ew, nullptr, 1);
    k_node2<<<NODE_BLOCKS, 256>>>(br2);

    launch_gemms(W1, b1, W2, b2, W3, b3, W4, b4, out);
}

// round 4
// speedup vs baseline: 1.2984x; 1.2984x over previous
#include <cuda_runtime.h>

#define N_NODES 160000
#define NODES_PER_GRAPH 20000
#define N_GRAPHS 8
#define N_EDGES 5120000
#define HID 16
#define O1 4000
#define O2 800
#define O3 160
#define NOUT 10

// -------- scratch (device globals: no allocation allowed) ----------------
// agg arrays obey a zero-invariant: zero at entry to every kernel_launch
// (zero-initialized at load; k_node1/k_node2 reset them after consuming).
__device__ __align__(16) float d_agg1[N_NODES];
__device__ __align__(16) float d_agg2[N_NODES];
__device__ __align__(16) float d_p[N_NODES];
__device__ __align__(16) float d_q[N_NODES];
__device__ __align__(16) float d_gT[NODES_PER_GRAPH * 8];   // [k][b]
__device__ __align__(16) float d_h1T[O1 * 8];               // [o][b]
__device__ __align__(16) float d_h2T[O2 * 8];
__device__ __align__(16) float d_h3T[O3 * 8];

// -------- scalar edge scatter: agg[tgt] += ew * val[src] -----------------
__global__ void k_scatter(const int* __restrict__ src, const int* __restrict__ tgt,
                          const float* __restrict__ ew, const float* __restrict__ val_in,
                          int pass) {
    const float* __restrict__ val = (pass == 0) ? val_in : d_p;
    float* __restrict__ agg = (pass == 0) ? d_agg1 : d_agg2;
    int t = blockIdx.x * blockDim.x + threadIdx.x;
    int e0 = t * 4;
    if (e0 + 3 < N_EDGES) {
        int4   s = *reinterpret_cast<const int4*>(src + e0);
        int4   g = *reinterpret_cast<const int4*>(tgt + e0);
        float4 w = *reinterpret_cast<const float4*>(ew + e0);
        atomicAdd(&agg[g.x], w.x * __ldg(&val[s.x]));
        atomicAdd(&agg[g.y], w.y * __ldg(&val[s.y]));
        atomicAdd(&agg[g.z], w.z * __ldg(&val[s.z]));
        atomicAdd(&agg[g.w], w.w * __ldg(&val[s.w]));
    } else if (e0 < N_EDGES) {
        for (int e = e0; e < N_EDGES; e++)
            atomicAdd(&agg[tgt[e]], ew[e] * __ldg(&val[src[e]]));
    }
}

// -------- per-node layer-1 + fold layer-2 matmuls to scalars -------------
__global__ void k_node1(const float* __restrict__ x,
                        const float* __restrict__ Wr1, const float* __restrict__ br1,
                        const float* __restrict__ Ws1, const float* __restrict__ Wr2,
                        const float* __restrict__ Ws2) {
    __shared__ float swr1[HID], sbr1[HID], sws1[HID], swr2[HID], sws2[HID];
    if (threadIdx.x < HID) {
        swr1[threadIdx.x] = Wr1[threadIdx.x];
        sbr1[threadIdx.x] = br1[threadIdx.x];
        sws1[threadIdx.x] = Ws1[threadIdx.x];
        swr2[threadIdx.x] = Wr2[threadIdx.x];
        sws2[threadIdx.x] = Ws2[threadIdx.x];
    }
    __syncthreads();
    int n = blockIdx.x * blockDim.x + threadIdx.x;
    if (n >= N_NODES) return;
    float a = d_agg1[n];
    d_agg1[n] = 0.f;                      // restore zero-invariant for next replay
    float xv = x[n];
    float p = 0.f, q = 0.f;
#pragma unroll
    for (int f = 0; f < HID; f++) {
        float h = fmaf(a, swr1[f], fmaf(xv, sws1[f], sbr1[f]));
        h = fmaxf(h, 0.f);
        p = fmaf(swr2[f], h, p);
        q = fmaf(sws2[f], h, q);
    }
    d_p[n] = p;
    d_q[n] = q;
}

// -------- per-node layer-2 epilogue; write gT [k][b] ---------------------
__global__ void k_node2(const float* __restrict__ br2) {
    int n = blockIdx.x * blockDim.x + threadIdx.x;
    if (n >= N_NODES) return;
    float h2 = d_agg2[n] + __ldg(br2) + d_q[n];
    d_agg2[n] = 0.f;                      // restore zero-invariant
    int b = n / NODES_PER_GRAPH;
    int i = n - b * NODES_PER_GRAPH;
    d_gT[i * 8 + b] = h2;
}

// -------- dense layer: outT[o][b] = act( sum_k W[o][k]*inT[k][b] + bias[o] )
// One block owns 8 output rows x 8 batches; each thread owns 4 consecutive k
// (stride 1024) so all loads are LDG.128. K must be a multiple of 4.
template <bool RELU>
__global__ void __launch_bounds__(256)
k_gemm8(const float* __restrict__ W, const float* __restrict__ bias,
        const float* __restrict__ inT, float* __restrict__ outT, int K) {
    const int tid = threadIdx.x;
    const int o0 = blockIdx.x * 8;
    float acc[8][8];
#pragma unroll
    for (int r = 0; r < 8; r++)
#pragma unroll
        for (int b = 0; b < 8; b++) acc[r][b] = 0.f;

    const float* Wb = W + (size_t)o0 * K;
    for (int k0 = tid * 4; k0 < K; k0 += 1024) {
        float4 w[8];
#pragma unroll
        for (int r = 0; r < 8; r++)
            w[r] = *reinterpret_cast<const float4*>(Wb + (size_t)r * K + k0);
#pragma unroll
        for (int kk = 0; kk < 4; kk++) {
            float4 g0 = *reinterpret_cast<const float4*>(inT + (k0 + kk) * 8);
            float4 g1 = *reinterpret_cast<const float4*>(inT + (k0 + kk) * 8 + 4);
            float gv[8] = {g0.x, g0.y, g0.z, g0.w, g1.x, g1.y, g1.z, g1.w};
#pragma unroll
            for (int r = 0; r < 8; r++) {
                float wv = (kk == 0) ? w[r].x : (kk == 1) ? w[r].y
                         : (kk == 2) ? w[r].z : w[r].w;
#pragma unroll
                for (int b = 0; b < 8; b++) acc[r][b] = fmaf(wv, gv[b], acc[r][b]);
            }
        }
    }

    // staged shared-memory reduction of 64 accumulators over 256 threads
    __shared__ float s[32 * 256];  // 32 KB
#pragma unroll
    for (int half = 0; half < 2; half++) {
        __syncthreads();
#pragma unroll
        for (int j = 0; j < 32; j++) {
            int idx = half * 32 + j;
            s[j * 256 + tid] = acc[idx >> 3][idx & 7];
        }
        __syncthreads();
        int j = tid >> 3;      // 0..31 : which value
        int part = tid & 7;    // 0..7  : which slice of 256 partials
        float v = 0.f;
#pragma unroll
        for (int t = 0; t < 32; t++) v += s[j * 256 + part + t * 8];
        v += __shfl_down_sync(0xffffffffu, v, 4, 8);
        v += __shfl_down_sync(0xffffffffu, v, 2, 8);
        v += __shfl_down_sync(0xffffffffu, v, 1, 8);
        if (part == 0) {
            int idx = half * 32 + j;
            int r = idx >> 3, b = idx & 7;
            float o = v + __ldg(&bias[o0 + r]);
            if (RELU) o = fmaxf(o, 0.f);
            outT[(o0 + r) * 8 + b] = o;
        }
    }
}

// -------- final 10x160 layer + log_softmax ------------------------------
__global__ void k_final(const float* __restrict__ W4, const float* __restrict__ b4,
                        float* __restrict__ out) {
    __shared__ float logits[N_GRAPHS][NOUT];
    int tid = threadIdx.x;
    if (tid < N_GRAPHS * NOUT) {
        int o = tid / N_GRAPHS;
        int b = tid % N_GRAPHS;
        float v = __ldg(&b4[o]);
        for (int k = 0; k < O3; k++)
            v = fmaf(__ldg(&W4[o * O3 + k]), d_h3T[k * 8 + b], v);
        logits[b][o] = v;
    }
    __syncthreads();
    if (tid < N_GRAPHS) {
        float m = -1e30f;
#pragma unroll
        for (int o = 0; o < NOUT; o++) m = fmaxf(m, logits[tid][o]);
        float sum = 0.f;
#pragma unroll
        for (int o = 0; o < NOUT; o++) sum += expf(logits[tid][o] - m);
        float lse = m + logf(sum);
#pragma unroll
        for (int o = 0; o < NOUT; o++) out[tid * NOUT + o] = logits[tid][o] - lse;
    }
}

void launch_gemms(const float* W1, const float* b1, const float* W2, const float* b2,
                  const float* W3, const float* b3, const float* W4, const float* b4,
                  float* out) {
    static float *p_gT = nullptr, *p_h1 = nullptr, *p_h2 = nullptr, *p_h3 = nullptr;
    if (!p_gT) {
        cudaGetSymbolAddress((void**)&p_gT, d_gT);
        cudaGetSymbolAddress((void**)&p_h1, d_h1T);
        cudaGetSymbolAddress((void**)&p_h2, d_h2T);
        cudaGetSymbolAddress((void**)&p_h3, d_h3T);
    }
    k_gemm8<true ><<<O1 / 8, 256>>>(W1, b1, p_gT, p_h1, NODES_PER_GRAPH);
    k_gemm8<true ><<<O2 / 8, 256>>>(W2, b2, p_h1, p_h2, O1);
    k_gemm8<true ><<<O3 / 8, 256>>>(W3, b3, p_h2, p_h3, O2);
    k_final<<<1, 128>>>(W4, b4, out);
}

extern "C" void kernel_launch(void* const* d_in, const int* in_sizes, int n_in,
                              void* d_out, int out_size) {
    const float* x   = (const float*)d_in[0];
    const float* ew  = (const float*)d_in[1];
    const float* Wr1 = (const float*)d_in[2];
    const float* br1 = (const float*)d_in[3];
    const float* Ws1 = (const float*)d_in[4];
    const float* Wr2 = (const float*)d_in[5];
    const float* br2 = (const float*)d_in[6];
    const float* Ws2 = (const float*)d_in[7];
    const float* W1  = (const float*)d_in[8];
    const float* b1  = (const float*)d_in[9];
    const float* W2  = (const float*)d_in[10];
    const float* b2  = (const float*)d_in[11];
    const float* W3  = (const float*)d_in[12];
    const float* b3  = (const float*)d_in[13];
    const float* W4  = (const float*)d_in[14];
    const float* b4  = (const float*)d_in[15];
    const int*   ei  = (const int*)d_in[16];
    float* out = (float*)d_out;

    const int* src = ei;
    const int* tgt = ei + N_EDGES;

    const int NODE_BLOCKS = (N_NODES + 255) / 256;
    const int EDGE_BLOCKS = (N_EDGES / 4 + 255) / 256;

    k_scatter<<<EDGE_BLOCKS, 256>>>(src, tgt, ew, x, 0);
    k_node1<<<NODE_BLOCKS, 256>>>(x, Wr1, br1, Ws1, Wr2, Ws2);
    k_scatter<<<EDGE_BLOCKS, 256>>>(src, tgt, ew, nullptr, 1);
    k_node2<<<NODE_BLOCKS, 256>>>(br2);

    launch_gemms(W1, b1, W2, b2, W3, b3, W4, b4, out);
}